// round 13
// baseline (speedup 1.0000x reference)
#include <cuda_runtime.h>
#include <cuda_fp16.h>
#include <cstdint>
#include <math.h>

namespace {
constexpr int Bb = 128;
constexpr int Qq = 512;
constexpr int Tt = 512;
constexpr int Dd = 256;
constexpr int QT = 64;            // queries per CTA
constexpr int THREADS = 512;      // 16 warps
constexpr int TTILE = 256;        // t-cols per pass; warp owns 32
constexpr int DCH = 16;           // d-cols per stage (one k16 step)
constexpr int NSTAGE = 32;        // 2 passes x 16 d-chunks
constexpr int QLDh = 264;         // Q smem ld in halves (528B rows -> 16B rotation)
constexpr int KLDh = 24;          // K smem ld in halves (48B rows, conflict-free)
constexpr int SLD = 520;          // S fp16 ld (1040B rows -> 16B rotation)
constexpr float SCALE = 0.0625f;  // 1/sqrt(256)

constexpr int KBUF    = 256 * KLDh * 2;        // 12288 B per K buffer (fp16)
constexpr int SM_Q    = 0;                     // 64*264*2 = 33792
constexpr int SM_K    = SM_Q + QT * QLDh * 2;  // 2 bufs -> 24576
constexpr int SM_S    = SM_K + 2 * KBUF;       // 64*520*2 = 66560
constexpr int SM_ROW  = SM_S + QT * SLD * 2;
constexpr int SM_RINV = SM_ROW + 256;
constexpr int SMEM_BYTES = SM_RINV + 256;      // ~125.4 KB -> 1 CTA/SM
}  // namespace

__device__ float g_partial[Bb * 8 * Tt];  // per-(batch,qtile) colsum partials
__device__ float g_pool[Bb * 4 * Dd];     // per-(batch,tslice) pooled partials

// PTX m16n8k16 f16 mma, fp32 accumulate; fragment layouts architecturally specified:
// A: a0(g, 2tg..+1) a1(g+8, 2tg..+1) a2(g, 8+2tg..+1) a3(g+8, 8+2tg..+1)   [half2]
// B: b0(k=2tg..+1, n=g) b1(k=8+2tg..+1, n=g)                               [half2]
// C: c0(g,2tg) c1(g,2tg+1) c2(g+8,2tg) c3(g+8,2tg+1)     [g=lane>>2, tg=lane&3]
__device__ __forceinline__ void mma_f16(float* c, const uint32_t* a, uint32_t b0,
                                        uint32_t b1) {
    asm volatile(
        "mma.sync.aligned.m16n8k16.row.col.f32.f16.f16.f32 "
        "{%0,%1,%2,%3}, {%4,%5,%6,%7}, {%8,%9}, {%0,%1,%2,%3};"
        : "+f"(c[0]), "+f"(c[1]), "+f"(c[2]), "+f"(c[3])
        : "r"(a[0]), "r"(a[1]), "r"(a[2]), "r"(a[3]), "r"(b0), "r"(b1));
}

// LDG one K chunk slice for this thread: row=tid/2, 8 floats at col8=(tid&1)*8.
__device__ __forceinline__ void ldg_stage(const float* __restrict__ Kg, int stage,
                                          int tid, float4* v) {
    const int p = stage >> 4, dc = stage & 15;
    const int row = tid >> 1, c8 = (tid & 1) * 8;
    const float* g = Kg + (size_t)(p * TTILE + row) * Dd + dc * DCH + c8;
    v[0] = ((const float4*)g)[0];
    v[1] = ((const float4*)g)[1];
}
// Convert + store this thread's 8 floats as fp16 into K buffer (16B STS).
__device__ __forceinline__ void sts_stage(char* smem, int buf, int tid, const float4* v) {
    const int row = tid >> 1, c8 = (tid & 1) * 8;
    __half* dst = (__half*)(smem + SM_K + buf * KBUF) + row * KLDh + c8;
    uint4 pack;
    ((__half2*)&pack)[0] = __floats2half2_rn(v[0].x, v[0].y);
    ((__half2*)&pack)[1] = __floats2half2_rn(v[0].z, v[0].w);
    ((__half2*)&pack)[2] = __floats2half2_rn(v[1].x, v[1].y);
    ((__half2*)&pack)[3] = __floats2half2_rn(v[1].z, v[1].w);
    *(uint4*)dst = pack;
}

// Per CTA: (batch, 64-query tile). S = softmax rows of scale*Q.K^T; write
// weight column-sum partial to g_partial (no atomics).
__global__ void __launch_bounds__(THREADS, 1)
score_kernel(const float* __restrict__ inputs, const float* __restrict__ query) {
    extern __shared__ char smem[];
    const int tid = threadIdx.x, wid = tid >> 5, lane = tid & 31;
    const int wq = wid >> 3;   // q-half (32 rows)
    const int wt = wid & 7;    // 32 t-cols within pass
    const int g = lane >> 2, tg = lane & 3;
    const int batch = blockIdx.x >> 3;
    const int q0 = (blockIdx.x & 7) * QT;

    const float* Qg = query + ((size_t)batch * Qq + q0) * Dd;
    const float* Kg = inputs + (size_t)batch * Tt * Dd;

    __half* Qh = (__half*)(smem + SM_Q);
    float* rowsum = (float*)(smem + SM_ROW);
    float* rinv = (float*)(smem + SM_RINV);
    __half* Sh = (__half*)(smem + SM_S);

    float4 pf[2][2];
    ldg_stage(Kg, 0, tid, pf[0]);  // prefetch 2 stages ahead
    ldg_stage(Kg, 1, tid, pf[1]);

    if (tid < QT) rowsum[tid] = 0.0f;

    // Stage Q as fp16 (scale folded): 64x256 -> 4096 float4, 8 per thread
#pragma unroll
    for (int it = 0; it < 8; ++it) {
        int i = tid + it * THREADS;
        int r = i >> 6, c4 = i & 63;
        float4 v = ((const float4*)Qg)[r * 64 + c4];
        uint2 pack;
        ((__half2*)&pack)[0] = __floats2half2_rn(v.x * SCALE, v.y * SCALE);
        ((__half2*)&pack)[1] = __floats2half2_rn(v.z * SCALE, v.w * SCALE);
        *(uint2*)(Qh + r * QLDh + c4 * 4) = pack;
    }

    float acc[2][4][4];  // [mi][ni][c]

    for (int stage = 0; stage < NSTAGE; ++stage) {
        const int buf = stage & 1, p = stage >> 4, dc = stage & 15;
        __syncthreads();  // stage 0: Q staged; later: buf's readers done
        sts_stage(smem, buf, tid, pf[buf]);
        if (stage + 2 < NSTAGE) ldg_stage(Kg, stage + 2, tid, pf[buf]);
        __syncthreads();

        if (dc == 0) {
#pragma unroll
            for (int mi = 0; mi < 2; ++mi)
#pragma unroll
                for (int ni = 0; ni < 4; ++ni)
#pragma unroll
                    for (int c = 0; c < 4; ++c) acc[mi][ni][c] = 0.0f;
        }
        const __half* Kh = (const __half*)(smem + SM_K + buf * KBUF);

        uint32_t a[2][4];
#pragma unroll
        for (int mi = 0; mi < 2; ++mi) {
            const __half* Ab = Qh + (wq * 32 + mi * 16 + g) * QLDh + dc * DCH + tg * 2;
            a[mi][0] = *(const uint32_t*)(Ab);
            a[mi][1] = *(const uint32_t*)(Ab + 8 * QLDh);
            a[mi][2] = *(const uint32_t*)(Ab + 8);
            a[mi][3] = *(const uint32_t*)(Ab + 8 * QLDh + 8);
        }
#pragma unroll
        for (int ni = 0; ni < 4; ++ni) {
            const __half* Bb_ = Kh + (wt * 32 + ni * 8 + g) * KLDh + tg * 2;
            uint32_t b0 = *(const uint32_t*)(Bb_);
            uint32_t b1 = *(const uint32_t*)(Bb_ + 8);
            mma_f16(acc[0][ni], a[0], b0, b1);
            mma_f16(acc[1][ni], a[1], b0, b1);
        }

        if (dc == 15) {
            // Register-direct epilogue for pass p: exp -> S (fp16), rowsum partials.
            float rsum[4] = {0.0f, 0.0f, 0.0f, 0.0f};
            const int tb = p * TTILE + wt * 32;
#pragma unroll
            for (int mi = 0; mi < 2; ++mi) {
                const int r = wq * 32 + mi * 16 + g;
#pragma unroll
                for (int ni = 0; ni < 4; ++ni) {
                    float e0 = __expf(acc[mi][ni][0]);
                    float e1 = __expf(acc[mi][ni][1]);
                    float e2 = __expf(acc[mi][ni][2]);
                    float e3 = __expf(acc[mi][ni][3]);
                    rsum[mi * 2 + 0] += e0 + e1;
                    rsum[mi * 2 + 1] += e2 + e3;
                    const int c = tb + ni * 8 + tg * 2;
                    *(__half2*)(Sh + r * SLD + c) = __floats2half2_rn(e0, e1);
                    *(__half2*)(Sh + (r + 8) * SLD + c) = __floats2half2_rn(e2, e3);
                }
            }
#pragma unroll
            for (int j = 0; j < 4; ++j) {
                rsum[j] += __shfl_xor_sync(0xffffffffu, rsum[j], 1);
                rsum[j] += __shfl_xor_sync(0xffffffffu, rsum[j], 2);
            }
            if (tg == 0) {
                atomicAdd(&rowsum[wq * 32 + g], rsum[0]);
                atomicAdd(&rowsum[wq * 32 + g + 8], rsum[1]);
                atomicAdd(&rowsum[wq * 32 + 16 + g], rsum[2]);
                atomicAdd(&rowsum[wq * 32 + 24 + g], rsum[3]);
            }
        }
    }
    __syncthreads();
    if (tid < QT) rinv[tid] = 1.0f / rowsum[tid];
    __syncthreads();

    // Column sums of normalized weights -> g_partial (one t per thread)
    const int t = tid;
    float s = 0.0f;
#pragma unroll 8
    for (int r = 0; r < QT; ++r) s += __half2float(Sh[r * SLD + t]) * rinv[r];
    g_partial[(size_t)blockIdx.x * Tt + t] = s;
}

// Stage 1 pool: (batch, t-slice of 128): g_pool[b,s,d] = sum_t c_t * V[t,d]
__global__ void __launch_bounds__(256)
pool_partial_kernel(const float* __restrict__ inputs) {
    __shared__ float c[128];
    const int b = blockIdx.x >> 2;
    const int t0 = (blockIdx.x & 3) * 128;
    if (threadIdx.x < 128) {
        float v = 0.0f;
#pragma unroll
        for (int j = 0; j < 8; ++j)
            v += g_partial[((size_t)b * 8 + j) * Tt + t0 + threadIdx.x];
        c[threadIdx.x] = v;
    }
    __syncthreads();

    const float* V = inputs + ((size_t)b * Tt + t0) * Dd;
    const int d = threadIdx.x;
    float a0 = 0.0f, a1 = 0.0f, a2 = 0.0f, a3 = 0.0f;
#pragma unroll 4
    for (int t = 0; t < 128; t += 4) {
        a0 += c[t + 0] * V[(size_t)(t + 0) * Dd + d];
        a1 += c[t + 1] * V[(size_t)(t + 1) * Dd + d];
        a2 += c[t + 2] * V[(size_t)(t + 2) * Dd + d];
        a3 += c[t + 3] * V[(size_t)(t + 3) * Dd + d];
    }
    g_pool[(size_t)blockIdx.x * Dd + d] = (a0 + a1) + (a2 + a3);
}

// Stage 2 pool: out[b,d] = sum_s g_pool[b,s,d]
__global__ void __launch_bounds__(256)
pool_reduce_kernel(float* __restrict__ out) {
    const int b = blockIdx.x, d = threadIdx.x;
    float s = 0.0f;
#pragma unroll
    for (int j = 0; j < 4; ++j) s += g_pool[((size_t)b * 4 + j) * Dd + d];
    out[b * Dd + d] = s;
}

extern "C" void kernel_launch(void* const* d_in, const int* in_sizes, int n_in,
                              void* d_out, int out_size) {
    const float* inputs = (const float*)d_in[0];  // [B, T, D]
    const float* query  = (const float*)d_in[1];  // [B, Q, D]
    float* out = (float*)d_out;                   // [B, D]

    cudaFuncSetAttribute(score_kernel,
                         cudaFuncAttributeMaxDynamicSharedMemorySize, SMEM_BYTES);

    score_kernel<<<Bb * (Qq / QT), THREADS, SMEM_BYTES>>>(inputs, query);
    pool_partial_kernel<<<Bb * 4, 256>>>(inputs);
    pool_reduce_kernel<<<Bb, 256>>>(out);
}

// round 14
// speedup vs baseline: 1.7208x; 1.7208x over previous
#include <cuda_runtime.h>
#include <cuda_fp16.h>
#include <cstdint>
#include <math.h>

namespace {
constexpr int Bb = 128;
constexpr int Qq = 512;
constexpr int Tt = 512;
constexpr int Dd = 256;
constexpr int QT = 64;            // queries per CTA
constexpr int THREADS = 512;      // 16 warps
constexpr int TTILE = 256;        // t-cols per pass; warp owns 32
constexpr int DCH = 32;           // d-cols per stage (two k16 steps)
constexpr int NSTAGE = 16;        // 2 passes x 8 d-chunks
constexpr int QLDh = 264;         // Q smem ld in halves (528B rows)
constexpr int KLDh = 40;          // K smem ld in halves (80B rows, conflict-free)
constexpr int SLD = 520;          // S fp16 ld (1040B rows)
constexpr float SCALE = 0.0625f;  // 1/sqrt(256)

constexpr int KBUF    = 256 * KLDh * 2;        // 20480 B per K buffer
constexpr int SM_Q    = 0;                     // 64*264*2 = 33792
constexpr int SM_K    = SM_Q + QT * QLDh * 2;  // 2 bufs -> 40960
constexpr int SM_S    = SM_K + 2 * KBUF;       // 64*520*2 = 66560
constexpr int SM_ROW  = SM_S + QT * SLD * 2;
constexpr int SM_RINV = SM_ROW + 256;
constexpr int SMEM_BYTES = SM_RINV + 256;      // ~142 KB -> 1 CTA/SM
}  // namespace

__device__ __half g_kf16[Bb * Tt * Dd];   // fp16 copy of inputs (32 MB)
__device__ float g_partial[Bb * 8 * Tt];  // per-(batch,qtile) colsum partials
__device__ float g_pool[Bb * 4 * Dd];     // per-(batch,tslice) pooled partials

__device__ __forceinline__ uint32_t smem_u32(const void* p) {
    uint32_t a;
    asm("{ .reg .u64 t; cvta.to.shared.u64 t, %1; cvt.u32.u64 %0, t; }" : "=r"(a) : "l"(p));
    return a;
}
// PTX m16n8k16 f16 mma, fp32 accumulate (layouts architecturally specified).
__device__ __forceinline__ void mma_f16(float* c, const uint32_t* a, uint32_t b0,
                                        uint32_t b1) {
    asm volatile(
        "mma.sync.aligned.m16n8k16.row.col.f32.f16.f16.f32 "
        "{%0,%1,%2,%3}, {%4,%5,%6,%7}, {%8,%9}, {%0,%1,%2,%3};"
        : "+f"(c[0]), "+f"(c[1]), "+f"(c[2]), "+f"(c[3])
        : "r"(a[0]), "r"(a[1]), "r"(a[2]), "r"(a[3]), "r"(b0), "r"(b1));
}

// Pre-pass: inputs fp32 -> fp16 (8 elems per thread).
__global__ void __launch_bounds__(256)
convert_kernel(const float* __restrict__ inputs) {
    const size_t i = ((size_t)blockIdx.x * 256 + threadIdx.x) * 8;
    float4 v0 = ((const float4*)(inputs + i))[0];
    float4 v1 = ((const float4*)(inputs + i))[1];
    uint4 pack;
    ((__half2*)&pack)[0] = __floats2half2_rn(v0.x, v0.y);
    ((__half2*)&pack)[1] = __floats2half2_rn(v0.z, v0.w);
    ((__half2*)&pack)[2] = __floats2half2_rn(v1.x, v1.y);
    ((__half2*)&pack)[3] = __floats2half2_rn(v1.z, v1.w);
    *(uint4*)(g_kf16 + i) = pack;
}

// cp.async one fp16 K chunk: 256 t-rows x 32 d-cols into buf stage&1.
// 16B copies: 4 per row, 1024 total, 2 per thread.
__device__ __forceinline__ void issue_stage(uint32_t sb, const __half* __restrict__ Kg,
                                            int stage, int tid) {
    const int buf = stage & 1, p = stage >> 3, dc = stage & 7;
    const __half* base = Kg + (size_t)p * TTILE * Dd + dc * DCH;
    const uint32_t dbase = sb + SM_K + buf * KBUF;
#pragma unroll
    for (int it = 0; it < 2; ++it) {
        int i = tid + it * THREADS;  // 0..1023
        int row = i >> 2, q = i & 3;
        uint32_t dst = dbase + (uint32_t)(row * KLDh + q * 8) * 2;
        const __half* g = base + (size_t)row * Dd + q * 8;
        asm volatile("cp.async.ca.shared.global [%0], [%1], 16;" :: "r"(dst), "l"(g));
    }
    asm volatile("cp.async.commit_group;" ::: "memory");
}

// Per CTA: (batch, 64-query tile). S = softmax rows of scale*Q.K^T; write
// weight column-sum partial to g_partial.
__global__ void __launch_bounds__(THREADS, 1)
score_kernel(const float* __restrict__ query) {
    extern __shared__ char smem[];
    const uint32_t sb = smem_u32(smem);
    const int tid = threadIdx.x, wid = tid >> 5, lane = tid & 31;
    const int wq = wid >> 3;   // q-half (32 rows)
    const int wt = wid & 7;    // 32 t-cols within pass
    const int g = lane >> 2, tg = lane & 3;
    const int batch = blockIdx.x >> 3;
    const int q0 = (blockIdx.x & 7) * QT;

    const float* Qg = query + ((size_t)batch * Qq + q0) * Dd;
    const __half* Kg = g_kf16 + (size_t)batch * Tt * Dd;

    __half* Qh = (__half*)(smem + SM_Q);
    float* rowsum = (float*)(smem + SM_ROW);
    float* rinv = (float*)(smem + SM_RINV);
    __half* Sh = (__half*)(smem + SM_S);

    issue_stage(sb, Kg, 0, tid);  // start K pipeline ASAP

    if (tid < QT) rowsum[tid] = 0.0f;

    // Stage Q as fp16 (scale folded): 64x256, 8 floats per thread
#pragma unroll
    for (int it = 0; it < 8; ++it) {
        int i = tid + it * THREADS;
        int r = i >> 6, c4 = i & 63;
        float4 v = ((const float4*)Qg)[r * 64 + c4];
        uint2 pack;
        ((__half2*)&pack)[0] = __floats2half2_rn(v.x * SCALE, v.y * SCALE);
        ((__half2*)&pack)[1] = __floats2half2_rn(v.z * SCALE, v.w * SCALE);
        *(uint2*)(Qh + r * QLDh + c4 * 4) = pack;
    }

    float acc[2][4][4];  // [mi][ni][c]

    for (int stage = 0; stage < NSTAGE; ++stage) {
        const int buf = stage & 1, p = stage >> 3, dc = stage & 7;
        asm volatile("cp.async.wait_group 0;" ::: "memory");
        __syncthreads();  // stage ready; prev compute done; Q staged (stage 0)
        if (stage + 1 < NSTAGE) issue_stage(sb, Kg, stage + 1, tid);

        if (dc == 0) {
#pragma unroll
            for (int mi = 0; mi < 2; ++mi)
#pragma unroll
                for (int ni = 0; ni < 4; ++ni)
#pragma unroll
                    for (int c = 0; c < 4; ++c) acc[mi][ni][c] = 0.0f;
        }
        const __half* Kh = (const __half*)(smem + SM_K + buf * KBUF);

#pragma unroll
        for (int ks = 0; ks < 2; ++ks) {
            const int col = dc * DCH + ks * 16 + tg * 2;
            uint32_t a[2][4];
#pragma unroll
            for (int mi = 0; mi < 2; ++mi) {
                const __half* Ab = Qh + (wq * 32 + mi * 16 + g) * QLDh + col;
                a[mi][0] = *(const uint32_t*)(Ab);
                a[mi][1] = *(const uint32_t*)(Ab + 8 * QLDh);
                a[mi][2] = *(const uint32_t*)(Ab + 8);
                a[mi][3] = *(const uint32_t*)(Ab + 8 * QLDh + 8);
            }
#pragma unroll
            for (int ni = 0; ni < 4; ++ni) {
                const __half* Bp = Kh + (wt * 32 + ni * 8 + g) * KLDh + ks * 16 + tg * 2;
                uint32_t b0 = *(const uint32_t*)(Bp);
                uint32_t b1 = *(const uint32_t*)(Bp + 8);
                mma_f16(acc[0][ni], a[0], b0, b1);
                mma_f16(acc[1][ni], a[1], b0, b1);
            }
        }

        if (dc == 7) {
            // Register-direct epilogue for pass p: exp -> S (fp16), rowsum partials.
            float rsum[4] = {0.0f, 0.0f, 0.0f, 0.0f};
            const int tb = p * TTILE + wt * 32;
#pragma unroll
            for (int mi = 0; mi < 2; ++mi) {
                const int r = wq * 32 + mi * 16 + g;
#pragma unroll
                for (int ni = 0; ni < 4; ++ni) {
                    float e0 = __expf(acc[mi][ni][0]);
                    float e1 = __expf(acc[mi][ni][1]);
                    float e2 = __expf(acc[mi][ni][2]);
                    float e3 = __expf(acc[mi][ni][3]);
                    rsum[mi * 2 + 0] += e0 + e1;
                    rsum[mi * 2 + 1] += e2 + e3;
                    const int c = tb + ni * 8 + tg * 2;
                    *(__half2*)(Sh + r * SLD + c) = __floats2half2_rn(e0, e1);
                    *(__half2*)(Sh + (r + 8) * SLD + c) = __floats2half2_rn(e2, e3);
                }
            }
#pragma unroll
            for (int j = 0; j < 4; ++j) {
                rsum[j] += __shfl_xor_sync(0xffffffffu, rsum[j], 1);
                rsum[j] += __shfl_xor_sync(0xffffffffu, rsum[j], 2);
            }
            if (tg == 0) {
                atomicAdd(&rowsum[wq * 32 + g], rsum[0]);
                atomicAdd(&rowsum[wq * 32 + g + 8], rsum[1]);
                atomicAdd(&rowsum[wq * 32 + 16 + g], rsum[2]);
                atomicAdd(&rowsum[wq * 32 + 24 + g], rsum[3]);
            }
        }
    }
    __syncthreads();
    if (tid < QT) rinv[tid] = 1.0f / rowsum[tid];
    __syncthreads();

    // Column sums of normalized weights -> g_partial (one t per thread)
    const int t = tid;
    float s = 0.0f;
#pragma unroll 8
    for (int r = 0; r < QT; ++r) s += __half2float(Sh[r * SLD + t]) * rinv[r];
    g_partial[(size_t)blockIdx.x * Tt + t] = s;
}

// Stage 1 pool: (batch, t-slice of 128): g_pool[b,s,d] = sum_t c_t * V[t,d]
__global__ void __launch_bounds__(256)
pool_partial_kernel(const float* __restrict__ inputs) {
    __shared__ float c[128];
    const int b = blockIdx.x >> 2;
    const int t0 = (blockIdx.x & 3) * 128;
    if (threadIdx.x < 128) {
        float v = 0.0f;
#pragma unroll
        for (int j = 0; j < 8; ++j)
            v += g_partial[((size_t)b * 8 + j) * Tt + t0 + threadIdx.x];
        c[threadIdx.x] = v;
    }
    __syncthreads();

    const float* V = inputs + ((size_t)b * Tt + t0) * Dd;
    const int d = threadIdx.x;
    float a0 = 0.0f, a1 = 0.0f, a2 = 0.0f, a3 = 0.0f;
#pragma unroll 4
    for (int t = 0; t < 128; t += 4) {
        a0 += c[t + 0] * V[(size_t)(t + 0) * Dd + d];
        a1 += c[t + 1] * V[(size_t)(t + 1) * Dd + d];
        a2 += c[t + 2] * V[(size_t)(t + 2) * Dd + d];
        a3 += c[t + 3] * V[(size_t)(t + 3) * Dd + d];
    }
    g_pool[(size_t)blockIdx.x * Dd + d] = (a0 + a1) + (a2 + a3);
}

// Stage 2 pool: out[b,d] = sum_s g_pool[b,s,d]
__global__ void __launch_bounds__(256)
pool_reduce_kernel(float* __restrict__ out) {
    const int b = blockIdx.x, d = threadIdx.x;
    float s = 0.0f;
#pragma unroll
    for (int j = 0; j < 4; ++j) s += g_pool[((size_t)b * 4 + j) * Dd + d];
    out[b * Dd + d] = s;
}

extern "C" void kernel_launch(void* const* d_in, const int* in_sizes, int n_in,
                              void* d_out, int out_size) {
    const float* inputs = (const float*)d_in[0];  // [B, T, D]
    const float* query  = (const float*)d_in[1];  // [B, Q, D]
    float* out = (float*)d_out;                   // [B, D]

    cudaFuncSetAttribute(score_kernel,
                         cudaFuncAttributeMaxDynamicSharedMemorySize, SMEM_BYTES);

    convert_kernel<<<(Bb * Tt * Dd) / (256 * 8), 256>>>(inputs);
    score_kernel<<<Bb * (Qq / QT), THREADS, SMEM_BYTES>>>(query);
    pool_partial_kernel<<<Bb * 4, 256>>>(inputs);
    pool_reduce_kernel<<<Bb, 256>>>(out);
}

// round 16
// speedup vs baseline: 1.9812x; 1.1513x over previous
#include <cuda_runtime.h>
#include <cuda_fp16.h>
#include <cstdint>
#include <math.h>

namespace {
constexpr int Bb = 128;
constexpr int Qq = 512;
constexpr int Tt = 512;
constexpr int Dd = 256;
constexpr int QT = 64;            // queries per CTA
constexpr int THREADS = 512;      // 16 warps
constexpr int TTILE = 256;        // t-cols per pass; warp owns 32
constexpr int DCH = 32;           // d-cols per stage (two k16 steps)
constexpr int NSTAGE = 16;        // 2 passes x 8 d-chunks
constexpr int QLDh = 264;         // Q smem ld in halves (528B rows; LDSM conflict-free)
constexpr int KLDh = 40;          // K smem ld in halves (80B rows; LDSM conflict-free)
constexpr int SLD = 520;          // S fp16 ld (1040B rows)
constexpr float SCALE = 0.0625f;  // 1/sqrt(256)

constexpr int KBUF    = 256 * KLDh * 2;        // 20480 B per K buffer
constexpr int SM_Q    = 0;                     // 64*264*2 = 33792
constexpr int SM_K    = SM_Q + QT * QLDh * 2;  // 2 bufs -> 40960
constexpr int SM_S    = SM_K + 2 * KBUF;       // 64*520*2 = 66560
constexpr int SM_ROW  = SM_S + QT * SLD * 2;
constexpr int SM_RINV = SM_ROW + 256;
constexpr int SMEM_BYTES = SM_RINV + 256;      // ~142 KB -> 1 CTA/SM
}  // namespace

__device__ __half g_kf16[Bb * Tt * Dd];   // fp16 copy of inputs (32 MB)
__device__ float g_partial[Bb * 8 * Tt];  // per-(batch,qtile) colsum partials

__device__ __forceinline__ uint32_t smem_u32(const void* p) {
    uint32_t a;
    asm("{ .reg .u64 t; cvta.to.shared.u64 t, %1; cvt.u32.u64 %0, t; }" : "=r"(a) : "l"(p));
    return a;
}
// PTX m16n8k16 f16 mma, fp32 accumulate (layouts architecturally specified).
__device__ __forceinline__ void mma_f16(float* c, const uint32_t* a, uint32_t b0,
                                        uint32_t b1) {
    asm volatile(
        "mma.sync.aligned.m16n8k16.row.col.f32.f16.f16.f32 "
        "{%0,%1,%2,%3}, {%4,%5,%6,%7}, {%8,%9}, {%0,%1,%2,%3};"
        : "+f"(c[0]), "+f"(c[1]), "+f"(c[2]), "+f"(c[3])
        : "r"(a[0]), "r"(a[1]), "r"(a[2]), "r"(a[3]), "r"(b0), "r"(b1));
}
#define LDSM_X4(r0, r1, r2, r3, addr)                                          \
    asm volatile("ldmatrix.sync.aligned.m8n8.x4.shared.b16 {%0,%1,%2,%3}, [%4];" \
                 : "=r"(r0), "=r"(r1), "=r"(r2), "=r"(r3) : "r"(addr))

// Pre-pass: inputs fp32 -> fp16; also zeroes `out` (used via atomics by pool).
__global__ void __launch_bounds__(256)
convert_kernel(const float* __restrict__ inputs, float* __restrict__ out) {
    const size_t i = ((size_t)blockIdx.x * 256 + threadIdx.x) * 8;
    float4 v0 = ((const float4*)(inputs + i))[0];
    float4 v1 = ((const float4*)(inputs + i))[1];
    uint4 pack;
    ((__half2*)&pack)[0] = __floats2half2_rn(v0.x, v0.y);
    ((__half2*)&pack)[1] = __floats2half2_rn(v0.z, v0.w);
    ((__half2*)&pack)[2] = __floats2half2_rn(v1.x, v1.y);
    ((__half2*)&pack)[3] = __floats2half2_rn(v1.z, v1.w);
    *(uint4*)(g_kf16 + i) = pack;
    if (blockIdx.x < (Bb * Dd) / 256) out[blockIdx.x * 256 + threadIdx.x] = 0.0f;
}

// cp.async one fp16 K chunk: 256 t-rows x 32 d-cols into buf stage&1.
__device__ __forceinline__ void issue_stage(uint32_t sb, const __half* __restrict__ Kg,
                                            int stage, int tid) {
    const int buf = stage & 1, p = stage >> 3, dc = stage & 7;
    const __half* base = Kg + (size_t)p * TTILE * Dd + dc * DCH;
    const uint32_t dbase = sb + SM_K + buf * KBUF;
#pragma unroll
    for (int it = 0; it < 2; ++it) {
        int i = tid + it * THREADS;  // 0..1023
        int row = i >> 2, q = i & 3;
        uint32_t dst = dbase + (uint32_t)(row * KLDh + q * 8) * 2;
        const __half* g = base + (size_t)row * Dd + q * 8;
        asm volatile("cp.async.ca.shared.global [%0], [%1], 16;" :: "r"(dst), "l"(g));
    }
    asm volatile("cp.async.commit_group;" ::: "memory");
}

// Per CTA: (batch, 64-query tile). S = softmax rows of scale*Q.K^T; write
// weight column-sum partial to g_partial.
__global__ void __launch_bounds__(THREADS, 1)
score_kernel(const float* __restrict__ query) {
    extern __shared__ char smem[];
    const uint32_t sb = smem_u32(smem);
    const int tid = threadIdx.x, wid = tid >> 5, lane = tid & 31;
    const int wq = wid >> 3;   // q-half (32 rows)
    const int wt = wid & 7;    // 32 t-cols within pass
    const int g = lane >> 2, tg = lane & 3;
    const int batch = blockIdx.x >> 3;
    const int q0 = (blockIdx.x & 7) * QT;

    const float* Qg = query + ((size_t)batch * Qq + q0) * Dd;
    const __half* Kg = g_kf16 + (size_t)batch * Tt * Dd;

    __half* Qh = (__half*)(smem + SM_Q);
    float* rowsum = (float*)(smem + SM_ROW);
    float* rinv = (float*)(smem + SM_RINV);
    __half* Sh = (__half*)(smem + SM_S);

    issue_stage(sb, Kg, 0, tid);  // start K pipeline ASAP

    if (tid < QT) rowsum[tid] = 0.0f;

    // Stage Q as fp16 (scale folded): 64x256, 8 floats per thread
#pragma unroll
    for (int it = 0; it < 8; ++it) {
        int i = tid + it * THREADS;
        int r = i >> 6, c4 = i & 63;
        float4 v = ((const float4*)Qg)[r * 64 + c4];
        uint2 pack;
        ((__half2*)&pack)[0] = __floats2half2_rn(v.x * SCALE, v.y * SCALE);
        ((__half2*)&pack)[1] = __floats2half2_rn(v.z * SCALE, v.w * SCALE);
        *(uint2*)(Qh + r * QLDh + c4 * 4) = pack;
    }

    // ldmatrix lane addresses.
    // A x4 mats: (rows0-7,k0-7)(rows8-15,k0-7)(rows0-7,k8-15)(rows8-15,k8-15)
    const uint32_t aLane =
        sb + SM_Q +
        (uint32_t)((wq * 32 + (lane & 7) + ((lane >> 3) & 1) * 8) * QLDh +
                   (lane >> 4) * 8) * 2;
    // B x4 mats: (t0-7,k0-7)(t0-7,k8-15)(t8-15,k0-7)(t8-15,k8-15)
    const uint32_t bLane =
        (uint32_t)((wt * 32 + (lane >> 4) * 8 + (lane & 7)) * KLDh +
                   ((lane >> 3) & 1) * 8) * 2;

    float acc[2][4][4];  // [mi][ni][c]

    for (int stage = 0; stage < NSTAGE; ++stage) {
        const int buf = stage & 1, p = stage >> 3, dc = stage & 7;
        asm volatile("cp.async.wait_group 0;" ::: "memory");
        __syncthreads();  // stage ready; prev compute done; Q staged (stage 0)
        if (stage + 1 < NSTAGE) issue_stage(sb, Kg, stage + 1, tid);

        if (dc == 0) {
#pragma unroll
            for (int mi = 0; mi < 2; ++mi)
#pragma unroll
                for (int ni = 0; ni < 4; ++ni)
#pragma unroll
                    for (int c = 0; c < 4; ++c) acc[mi][ni][c] = 0.0f;
        }
        const uint32_t kb = sb + SM_K + buf * KBUF + bLane;

#pragma unroll
        for (int ks = 0; ks < 2; ++ks) {
            // A column offset within full Q tile; B offset within 32-col stage buf.
            const uint32_t aCol = (uint32_t)(dc * DCH + ks * 16) * 2;
            const uint32_t bCol = (uint32_t)(ks * 16) * 2;
            uint32_t a[2][4], b[8];
            LDSM_X4(a[0][0], a[0][1], a[0][2], a[0][3], aLane + aCol);
            LDSM_X4(a[1][0], a[1][1], a[1][2], a[1][3],
                    aLane + 16 * QLDh * 2 + aCol);
            LDSM_X4(b[0], b[1], b[2], b[3], kb + bCol);
            LDSM_X4(b[4], b[5], b[6], b[7], kb + 16 * KLDh * 2 + bCol);
#pragma unroll
            for (int ni = 0; ni < 4; ++ni) {
                mma_f16(acc[0][ni], a[0], b[ni * 2], b[ni * 2 + 1]);
                mma_f16(acc[1][ni], a[1], b[ni * 2], b[ni * 2 + 1]);
            }
        }

        if (dc == 7) {
            // Register-direct epilogue for pass p: exp -> S (fp16), rowsum partials.
            float rsum[4] = {0.0f, 0.0f, 0.0f, 0.0f};
            const int tb = p * TTILE + wt * 32;
#pragma unroll
            for (int mi = 0; mi < 2; ++mi) {
                const int r = wq * 32 + mi * 16 + g;
#pragma unroll
                for (int ni = 0; ni < 4; ++ni) {
                    float e0 = __expf(acc[mi][ni][0]);
                    float e1 = __expf(acc[mi][ni][1]);
                    float e2 = __expf(acc[mi][ni][2]);
                    float e3 = __expf(acc[mi][ni][3]);
                    rsum[mi * 2 + 0] += e0 + e1;
                    rsum[mi * 2 + 1] += e2 + e3;
                    const int c = tb + ni * 8 + tg * 2;
                    *(__half2*)(Sh + r * SLD + c) = __floats2half2_rn(e0, e1);
                    *(__half2*)(Sh + (r + 8) * SLD + c) = __floats2half2_rn(e2, e3);
                }
            }
#pragma unroll
            for (int j = 0; j < 4; ++j) {
                rsum[j] += __shfl_xor_sync(0xffffffffu, rsum[j], 1);
                rsum[j] += __shfl_xor_sync(0xffffffffu, rsum[j], 2);
            }
            if (tg == 0) {
                atomicAdd(&rowsum[wq * 32 + g], rsum[0]);
                atomicAdd(&rowsum[wq * 32 + g + 8], rsum[1]);
                atomicAdd(&rowsum[wq * 32 + 16 + g], rsum[2]);
                atomicAdd(&rowsum[wq * 32 + 24 + g], rsum[3]);
            }
        }
    }
    __syncthreads();
    if (tid < QT) rinv[tid] = 1.0f / rowsum[tid];
    __syncthreads();

    // Column sums of normalized weights -> g_partial (one t per thread)
    const int t = tid;
    float s = 0.0f;
#pragma unroll 8
    for (int r = 0; r < QT; ++r) s += __half2float(Sh[r * SLD + t]) * rinv[r];
    g_partial[(size_t)blockIdx.x * Tt + t] = s;
}

// Pool: (batch, t-slice of 64): out[b,d] += sum_t c_t * V[t,d], V in fp16.
__global__ void __launch_bounds__(128)
pool_kernel(float* __restrict__ out) {
    __shared__ float c[64];
    const int b = blockIdx.x >> 3;
    const int t0 = (blockIdx.x & 7) * 64;
    if (threadIdx.x < 64) {
        float v = 0.0f;
#pragma unroll
        for (int j = 0; j < 8; ++j)
            v += g_partial[((size_t)b * 8 + j) * Tt + t0 + threadIdx.x];
        c[threadIdx.x] = v;
    }
    __syncthreads();

    const __half* V = g_kf16 + ((size_t)b * Tt + t0) * Dd;
    const int d2 = threadIdx.x;  // half2 column index
    float ax = 0.0f, ay = 0.0f;
#pragma unroll 8
    for (int t = 0; t < 64; ++t) {
        float2 f = __half22float2(*(const __half2*)(V + (size_t)t * Dd + d2 * 2));
        ax += c[t] * f.x;
        ay += c[t] * f.y;
    }
    atomicAdd(&out[b * Dd + d2 * 2], ax);
    atomicAdd(&out[b * Dd + d2 * 2 + 1], ay);
}

extern "C" void kernel_launch(void* const* d_in, const int* in_sizes, int n_in,
                              void* d_out, int out_size) {
    const float* inputs = (const float*)d_in[0];  // [B, T, D]
    const float* query  = (const float*)d_in[1];  // [B, Q, D]
    float* out = (float*)d_out;                   // [B, D]

    cudaFuncSetAttribute(score_kernel,
                         cudaFuncAttributeMaxDynamicSharedMemorySize, SMEM_BYTES);

    convert_kernel<<<(Bb * Tt * Dd) / (256 * 8), 256>>>(inputs, out);
    score_kernel<<<Bb * (Qq / QT), THREADS, SMEM_BYTES>>>(query);
    pool_kernel<<<Bb * 8, 128>>>(out);
}